// round 5
// baseline (speedup 1.0000x reference)
#include <cuda_runtime.h>
#include <cuda_bf16.h>
#include <cstdint>
#include <math.h>

using bf16 = __nv_bfloat16;

#define TT 64
#define BB 64
#define EE 512
#define HH 1024
#define SS 128
#define VV 1024

// ---- persistent scratch (device globals; no allocation) ----
__device__ __align__(16) bf16 g_Whi[2][2048u*4096u];  // LSTM weights k-major, gate-interleaved cols
__device__ __align__(16) bf16 g_Wlo[2][2048u*4096u];
__device__ __align__(16) bf16 g_W1hi[1024u*1024u];
__device__ __align__(16) bf16 g_W1lo[1024u*1024u];
__device__ __align__(16) bf16 g_W2hi[2048u*512u];
__device__ __align__(16) bf16 g_W2lo[2048u*512u];
__device__ __align__(16) bf16 g_xhi[4096u*512u];      // all-t embeddings
__device__ __align__(16) bf16 g_xlo[4096u*512u];
__device__ float g_xp[(size_t)4096*4096];             // precomputed x@Wx (perm cols), per t
__device__ __align__(16) bf16 g_a0hi[(size_t)TT*BB*1536];  // per-t layer0 [out|h0]
__device__ __align__(16) bf16 g_a0lo[(size_t)TT*BB*1536];
__device__ __align__(16) bf16 g_a1hi[BB*2048];             // layer1 [h0|h1prev]
__device__ __align__(16) bf16 g_a1lo[BB*2048];
__device__ __align__(16) bf16 g_aqhi[BB*1024];
__device__ __align__(16) bf16 g_aqlo[BB*1024];
__device__ __align__(16) bf16 g_aohi[BB*2048];             // [attended|h1]
__device__ __align__(16) bf16 g_aolo[BB*2048];
__device__ float g_qP[8][BB*1024];
__device__ float g_oP[16][BB*512];
__device__ float g_bsum[2*4096];     // bih+bhh, permuted
__device__ float g_c[2][BB*1024];

// ---- helpers ----
__device__ __forceinline__ void splitbf(float x, bf16* h, bf16* l) {
    bf16 hi = __float2bfloat16(x);
    *h = hi;
    *l = __float2bfloat16(x - __bfloat162float(hi));
}

__device__ __forceinline__ void cp16(bf16* s, const bf16* g) {
    uint32_t sa = (uint32_t)__cvta_generic_to_shared(s);
    asm volatile("cp.async.cg.shared.global [%0], [%1], 16;" :: "r"(sa), "l"(g) : "memory");
}

// ---- generic split-bf16 GEMM (used for q, out-proj, x-precompute) ----
// grid(N/64, splitK, M/64). Cp: [y][M][N] with row block z.
__global__ __launch_bounds__(256, 2) void gemm_split3(
    const bf16* __restrict__ Ahi, const bf16* __restrict__ Alo, int lda,
    const bf16* __restrict__ Bhi, const bf16* __restrict__ Blo, int ldb,
    float* __restrict__ Cp, int N, int Ksplit)
{
    __shared__ bf16 As[2][64][64];
    __shared__ bf16 Bs[2][64][64];
    const int tid = threadIdx.x, lane = tid & 31, wp = tid >> 5;
    const int wm = wp >> 2, wn = wp & 3;
    const int nb = blockIdx.x * 64;
    const int k0 = blockIdx.y * Ksplit;
    const size_t rowOff = (size_t)blockIdx.z * 64;
    const int nk = Ksplit >> 6;
    const int iters = 3 * nk;
    const bf16* At[3] = {Ahi + rowOff * lda, Alo + rowOff * lda, Ahi + rowOff * lda};
    const bf16* Bt[3] = {Bhi, Bhi, Blo};

    float acc[2][2][4];
#pragma unroll
    for (int i = 0; i < 2; i++)
#pragma unroll
        for (int j = 0; j < 2; j++)
#pragma unroll
            for (int r = 0; r < 4; r++) acc[i][j][r] = 0.f;

    auto issue = [&](int it, int buf) {
        int term = it / nk;
        int kb = k0 + (it - term * nk) * 64;
        const bf16* Ag = At[term];
        const bf16* Bg = Bt[term];
#pragma unroll
        for (int r = 0; r < 2; r++) {
            int ch = tid + 256 * r, row = ch >> 3, c8 = ch & 7;
            cp16(&As[buf][row][((c8 ^ (row & 7)) << 3)], Ag + (size_t)row * lda + kb + (c8 << 3));
            cp16(&Bs[buf][row][((c8 ^ (row & 7)) << 3)], Bg + (size_t)(kb + row) * ldb + nb + (c8 << 3));
        }
        asm volatile("cp.async.commit_group;");
    };

    issue(0, 0);
    for (int it = 0; it < iters; ++it) {
        int buf = it & 1;
        if (it + 1 < iters) {
            issue(it + 1, buf ^ 1);
            asm volatile("cp.async.wait_group 1;");
        } else {
            asm volatile("cp.async.wait_group 0;");
        }
        __syncthreads();
#pragma unroll
        for (int kk = 0; kk < 4; kk++) {
            uint32_t a[2][4], b[2][2];
#pragma unroll
            for (int mi = 0; mi < 2; mi++) {
                int m = (wm << 5) + (mi << 4) + (lane & 15);
                int pc = ((kk << 1) + (lane >> 4)) ^ (m & 7);
                uint32_t ad = (uint32_t)__cvta_generic_to_shared(&As[buf][m][pc << 3]);
                asm volatile("ldmatrix.sync.aligned.m8n8.x4.shared.b16 {%0,%1,%2,%3},[%4];"
                             : "=r"(a[mi][0]), "=r"(a[mi][1]), "=r"(a[mi][2]), "=r"(a[mi][3]) : "r"(ad));
            }
#pragma unroll
            for (int ni = 0; ni < 2; ni++) {
                int kr = (kk << 4) + (lane & 15);
                int pc = ((wn << 1) + ni) ^ (kr & 7);
                uint32_t ad = (uint32_t)__cvta_generic_to_shared(&Bs[buf][kr][pc << 3]);
                asm volatile("ldmatrix.sync.aligned.m8n8.x2.trans.shared.b16 {%0,%1},[%2];"
                             : "=r"(b[ni][0]), "=r"(b[ni][1]) : "r"(ad));
            }
#pragma unroll
            for (int mi = 0; mi < 2; mi++)
#pragma unroll
                for (int ni = 0; ni < 2; ni++)
                    asm volatile(
                        "mma.sync.aligned.m16n8k16.row.col.f32.bf16.bf16.f32 "
                        "{%0,%1,%2,%3},{%4,%5,%6,%7},{%8,%9},{%0,%1,%2,%3};"
                        : "+f"(acc[mi][ni][0]), "+f"(acc[mi][ni][1]), "+f"(acc[mi][ni][2]), "+f"(acc[mi][ni][3])
                        : "r"(a[mi][0]), "r"(a[mi][1]), "r"(a[mi][2]), "r"(a[mi][3]),
                          "r"(b[ni][0]), "r"(b[ni][1]));
        }
        __syncthreads();
    }

    float* C = Cp + ((size_t)blockIdx.y * gridDim.z + blockIdx.z) * 64 * N;
#pragma unroll
    for (int mi = 0; mi < 2; mi++)
#pragma unroll
        for (int ni = 0; ni < 2; ni++) {
            int row = (wm << 5) + (mi << 4) + (lane >> 2);
            int col = nb + (wn << 4) + (ni << 3) + ((lane & 3) << 1);
            C[(size_t)row * N + col]           = acc[mi][ni][0];
            C[(size_t)row * N + col + 1]       = acc[mi][ni][1];
            C[(size_t)(row + 8) * N + col]     = acc[mi][ni][2];
            C[(size_t)(row + 8) * N + col + 1] = acc[mi][ni][3];
        }
}

// ---- LSTM GEMM with fused cell epilogue (gate-interleaved cols) ----
// 64x32 tile, full K, grid=128 blocks, 256 threads.
__global__ __launch_bounds__(256, 1) void gemm_lstm(
    const bf16* __restrict__ Ahi, const bf16* __restrict__ Alo, int lda, int Kterm,
    const bf16* __restrict__ Bhi, const bf16* __restrict__ Blo,
    const float* __restrict__ xp,    // [64][4096] or null
    const float* __restrict__ bsum,  // [4096] permuted
    float* __restrict__ c,           // [64*1024]
    bf16* d0h, bf16* d0l, int s0,
    bf16* d1h, bf16* d1l, int s1,
    bf16* d2h, bf16* d2l, int s2)
{
    __shared__ bf16 As[2][64][64];
    __shared__ bf16 Bs[2][64][40];
    __shared__ float Cs[64][33];
    const int tid = threadIdx.x, lane = tid & 31, wp = tid >> 5;
    const int wm = wp >> 2, wn = wp & 3;  // 2x4 warps over 64x32
    const int nb = blockIdx.x * 32;
    const int jb = nb >> 2;
    const int nk = Kterm >> 6;
    const int iters = 3 * nk;
    const bf16* At[3] = {Ahi, Alo, Ahi};
    const bf16* Bt[3] = {Bhi, Bhi, Blo};

    float acc[2][4];
#pragma unroll
    for (int i = 0; i < 2; i++)
#pragma unroll
        for (int r = 0; r < 4; r++) acc[i][r] = 0.f;

    auto issue = [&](int it, int buf) {
        int term = it / nk;
        int kb = (it - term * nk) * 64;
        const bf16* Ag = At[term];
        const bf16* Bg = Bt[term];
#pragma unroll
        for (int r = 0; r < 2; r++) {
            int ch = tid + 256 * r, row = ch >> 3, c8 = ch & 7;
            cp16(&As[buf][row][((c8 ^ (row & 7)) << 3)], Ag + (size_t)row * lda + kb + (c8 << 3));
        }
        {
            int row = tid >> 2, c4 = tid & 3;
            cp16(&Bs[buf][row][c4 << 3], Bg + (size_t)(kb + row) * 4096 + nb + (c4 << 3));
        }
        asm volatile("cp.async.commit_group;");
    };

    issue(0, 0);
    for (int it = 0; it < iters; ++it) {
        int buf = it & 1;
        if (it + 1 < iters) {
            issue(it + 1, buf ^ 1);
            asm volatile("cp.async.wait_group 1;");
        } else {
            asm volatile("cp.async.wait_group 0;");
        }
        __syncthreads();
#pragma unroll
        for (int kk = 0; kk < 4; kk++) {
            uint32_t a[2][4], b[2];
#pragma unroll
            for (int mi = 0; mi < 2; mi++) {
                int m = (wm << 5) + (mi << 4) + (lane & 15);
                int pc = ((kk << 1) + (lane >> 4)) ^ (m & 7);
                uint32_t ad = (uint32_t)__cvta_generic_to_shared(&As[buf][m][pc << 3]);
                asm volatile("ldmatrix.sync.aligned.m8n8.x4.shared.b16 {%0,%1,%2,%3},[%4];"
                             : "=r"(a[mi][0]), "=r"(a[mi][1]), "=r"(a[mi][2]), "=r"(a[mi][3]) : "r"(ad));
            }
            {
                int kr = (kk << 4) + (lane & 15);
                uint32_t ad = (uint32_t)__cvta_generic_to_shared(&Bs[buf][kr][wn << 3]);
                asm volatile("ldmatrix.sync.aligned.m8n8.x2.trans.shared.b16 {%0,%1},[%2];"
                             : "=r"(b[0]), "=r"(b[1]) : "r"(ad));
            }
#pragma unroll
            for (int mi = 0; mi < 2; mi++)
                asm volatile(
                    "mma.sync.aligned.m16n8k16.row.col.f32.bf16.bf16.f32 "
                    "{%0,%1,%2,%3},{%4,%5,%6,%7},{%8,%9},{%0,%1,%2,%3};"
                    : "+f"(acc[mi][0]), "+f"(acc[mi][1]), "+f"(acc[mi][2]), "+f"(acc[mi][3])
                    : "r"(a[mi][0]), "r"(a[mi][1]), "r"(a[mi][2]), "r"(a[mi][3]),
                      "r"(b[0]), "r"(b[1]));
        }
        __syncthreads();
    }

    // accumulators -> smem
#pragma unroll
    for (int mi = 0; mi < 2; mi++) {
        int row = (wm << 5) + (mi << 4) + (lane >> 2);
        int col = (wn << 3) + ((lane & 3) << 1);
        Cs[row][col]     = acc[mi][0];
        Cs[row][col + 1] = acc[mi][1];
        Cs[row + 8][col]     = acc[mi][2];
        Cs[row + 8][col + 1] = acc[mi][3];
    }
    __syncthreads();

    // fused cell update: 64 batches x 8 j per block
#pragma unroll
    for (int r = 0; r < 2; r++) {
        int e = tid + 256 * r;
        int b = e >> 3, jl = e & 7;
        int jg = jb + jl;
        float g4[4];
#pragma unroll
        for (int g = 0; g < 4; g++) {
            float v = Cs[b][jl * 4 + g] + bsum[nb + jl * 4 + g];
            if (xp) v += xp[(size_t)b * 4096 + nb + jl * 4 + g];
            g4[g] = v;
        }
        float si = 1.f / (1.f + expf(-g4[0]));
        float sf = 1.f / (1.f + expf(-g4[1]));
        float so = 1.f / (1.f + expf(-g4[3]));
        int ci = b * 1024 + jg;
        float cn = sf * c[ci] + si * tanhf(g4[2]);
        c[ci] = cn;
        float h = so * tanhf(cn);
        bf16 hi, lo;
        splitbf(h, &hi, &lo);
        if (d0h) { d0h[(size_t)b * s0 + jg] = hi; d0l[(size_t)b * s0 + jg] = lo; }
        if (d1h) { d1h[(size_t)b * s1 + jg] = hi; d1l[(size_t)b * s1 + jg] = lo; }
        if (d2h) { d2h[(size_t)b * s2 + jg] = hi; d2l[(size_t)b * s2 + jg] = lo; }
    }
}

// ---- attention: combine qP + b1, scores, softmax, attended -> ao slot0 ----
__global__ __launch_bounds__(512) void attn_k(const float* __restrict__ qP,
                                              const float* __restrict__ b1,
                                              const float* __restrict__ enc,
                                              bf16* __restrict__ aoh, bf16* __restrict__ aol)
{
    __shared__ float qs[1024];
    __shared__ float sc[128];
    int b = blockIdx.x, tid = threadIdx.x, lane = tid & 31, wp = tid >> 5;
    for (int v = tid; v < 1024; v += 512) {
        float s = b1[v];
#pragma unroll
        for (int p = 0; p < 8; p++) s += qP[(size_t)p * BB * 1024 + (size_t)b * 1024 + v];
        qs[v] = s;
    }
    __syncthreads();
    const float* eb = enc + (size_t)b * SS * VV;
    const float4* q4 = (const float4*)qs;
    for (int s = wp; s < SS; s += 16) {
        const float4* e4 = (const float4*)(eb + (size_t)s * VV);
        float acc = 0.f;
#pragma unroll 2
        for (int i = lane; i < 256; i += 32) {
            float4 ev = e4[i], qv = q4[i];
            acc += qv.x * ev.x + qv.y * ev.y + qv.z * ev.z + qv.w * ev.w;
        }
#pragma unroll
        for (int o = 16; o > 0; o >>= 1) acc += __shfl_xor_sync(0xffffffffu, acc, o);
        if (lane == 0) sc[s] = acc;
    }
    __syncthreads();
    if (wp == 0) {
        float m = -1e30f;
#pragma unroll
        for (int i = 0; i < 4; i++) m = fmaxf(m, sc[lane + 32 * i]);
#pragma unroll
        for (int o = 16; o > 0; o >>= 1) m = fmaxf(m, __shfl_xor_sync(0xffffffffu, m, o));
        float ex[4], sum = 0.f;
#pragma unroll
        for (int i = 0; i < 4; i++) { ex[i] = expf(sc[lane + 32 * i] - m); sum += ex[i]; }
#pragma unroll
        for (int o = 16; o > 0; o >>= 1) sum += __shfl_xor_sync(0xffffffffu, sum, o);
        float inv = 1.f / sum;
#pragma unroll
        for (int i = 0; i < 4; i++) sc[lane + 32 * i] = ex[i] * inv;
    }
    __syncthreads();
    float a0 = 0.f, a1 = 0.f;
#pragma unroll 4
    for (int s = 0; s < SS; s++) {
        float w = sc[s];
        float2 ev = *(const float2*)(eb + (size_t)s * VV + 2 * tid);
        a0 += w * ev.x;
        a1 += w * ev.y;
    }
    bf16 hi, lo;
    splitbf(a0, &hi, &lo);
    aoh[(size_t)b * 2048 + 2 * tid] = hi; aol[(size_t)b * 2048 + 2 * tid] = lo;
    splitbf(a1, &hi, &lo);
    aoh[(size_t)b * 2048 + 2 * tid + 1] = hi; aol[(size_t)b * 2048 + 2 * tid + 1] = lo;
}

// ---- output: combine oP + b2, tanh, write d_out and input-feed slot ----
__global__ void out_k(const float* __restrict__ oP, const float* __restrict__ b2,
                      float* __restrict__ out, int t, bf16* nxh, bf16* nxl)
{
    int idx = blockIdx.x * blockDim.x + threadIdx.x;  // 64*512
    int b = idx >> 9, e = idx & 511;
    float s = b2[e];
#pragma unroll
    for (int p = 0; p < 16; p++) s += oP[(size_t)p * BB * 512 + idx];
    float o = tanhf(s);
    out[((size_t)b * TT + t) * EE + e] = o;
    if (nxh) {
        bf16 hi, lo;
        splitbf(o, &hi, &lo);
        nxh[(size_t)b * 1536 + e] = hi;
        nxl[(size_t)b * 1536 + e] = lo;
    }
}

// ---- transpose + split fp32 [R][C] -> bf16 hi/lo [C][R], optional gate-perm cols ----
__global__ void tsplit(const float* __restrict__ src, bf16* __restrict__ dhi,
                       bf16* __restrict__ dlo, int R, int C, int ldd, int perm)
{
    __shared__ float t[32][33];
    int kb = blockIdx.x << 5, nbs = blockIdx.y << 5;
    int tx = threadIdx.x, ty = threadIdx.y;  // 32x8
    for (int i = ty; i < 32; i += 8) t[i][tx] = src[(size_t)(nbs + i) * C + kb + tx];
    __syncthreads();
    for (int i = ty; i < 32; i += 8) {
        float v = t[tx][i];
        int n = nbs + tx;
        int pn = perm ? ((n & 1023) * 4 + (n >> 10)) : n;
        size_t o = (size_t)(kb + i) * ldd + pn;
        bf16 hi, lo;
        splitbf(v, &hi, &lo);
        dhi[o] = hi; dlo[o] = lo;
    }
}

// ---- combined, permuted biases ----
__global__ void bias_k(const float* __restrict__ bih, const float* __restrict__ bhh)
{
    int idx = blockIdx.x * blockDim.x + threadIdx.x;
    if (idx >= 8192) return;
    int l = idx >> 12, n = idx & 4095;
    int p = (n & 1023) * 4 + (n >> 10);
    g_bsum[l * 4096 + p] = bih[(size_t)l * 4096 + n] + bhh[(size_t)l * 4096 + n];
}

// ---- embed all timesteps into Xall ----
__global__ void embed_k(const int* __restrict__ tgt, const float* __restrict__ emb)
{
    int idx = blockIdx.x * blockDim.x + threadIdx.x;
    if (idx >= TT * BB * EE) return;
    int e = idx & 511, tb = idx >> 9;
    int b = tb & 63, t = tb >> 6;
    int tok = tgt[t * BB + b];
    float v = emb[(size_t)tok * EE + e];
    size_t o = ((size_t)t * BB + b) * 512 + e;
    bf16 hi, lo;
    splitbf(v, &hi, &lo);
    g_xhi[o] = hi; g_xlo[o] = lo;
}

// ---- init: c=0, a0[0]=[out0|h0init], a1 slot1 = h1init ----
__global__ void init_k(const float* __restrict__ out0, const float* __restrict__ hinit)
{
    int idx = blockIdx.x * blockDim.x + threadIdx.x;
    if (idx >= BB * HH) return;
    int b = idx >> 10, j = idx & 1023;
    g_c[0][idx] = 0.f; g_c[1][idx] = 0.f;
    bf16 hi, lo;
    splitbf(hinit[(size_t)BB * HH + idx], &hi, &lo);  // layer1 h init
    g_a1hi[(size_t)b * 2048 + 1024 + j] = hi;
    g_a1lo[(size_t)b * 2048 + 1024 + j] = lo;
    splitbf(hinit[idx], &hi, &lo);                    // layer0 h init
    g_a0hi[(size_t)b * 1536 + 512 + j] = hi;
    g_a0lo[(size_t)b * 1536 + 512 + j] = lo;
    if (j < 512) {
        splitbf(out0[(size_t)b * EE + j], &hi, &lo);  // input feed init
        g_a0hi[(size_t)b * 1536 + j] = hi;
        g_a0lo[(size_t)b * 1536 + j] = lo;
    }
}

extern "C" void kernel_launch(void* const* d_in, const int* in_sizes, int n_in,
                              void* d_out, int out_size)
{
    const int*   tgt   = (const int*)d_in[0];
    const float* enc   = (const float*)d_in[1];
    const float* emb   = (const float*)d_in[2];
    const float* out0  = (const float*)d_in[3];
    const float* hinit = (const float*)d_in[4];
    const float* Wih   = (const float*)d_in[5];
    const float* Whh   = (const float*)d_in[6];
    const float* bih   = (const float*)d_in[7];
    const float* bhh   = (const float*)d_in[8];
    const float* W1    = (const float*)d_in[9];
    const float* b1    = (const float*)d_in[10];
    const float* W2    = (const float*)d_in[11];
    const float* b2    = (const float*)d_in[12];
    float* out = (float*)d_out;

    bf16 *Whi, *Wlo, *W1h, *W1l, *W2h, *W2l, *xh, *xl;
    bf16 *a0h, *a0l, *a1h, *a1l, *aqh, *aql, *aoh, *aol;
    float *qP, *oP, *cst, *xp, *bsum;
    cudaGetSymbolAddress((void**)&Whi, g_Whi);
    cudaGetSymbolAddress((void**)&Wlo, g_Wlo);
    cudaGetSymbolAddress((void**)&W1h, g_W1hi);
    cudaGetSymbolAddress((void**)&W1l, g_W1lo);
    cudaGetSymbolAddress((void**)&W2h, g_W2hi);
    cudaGetSymbolAddress((void**)&W2l, g_W2lo);
    cudaGetSymbolAddress((void**)&xh,  g_xhi);
    cudaGetSymbolAddress((void**)&xl,  g_xlo);
    cudaGetSymbolAddress((void**)&xp,  g_xp);
    cudaGetSymbolAddress((void**)&a0h, g_a0hi);
    cudaGetSymbolAddress((void**)&a0l, g_a0lo);
    cudaGetSymbolAddress((void**)&a1h, g_a1hi);
    cudaGetSymbolAddress((void**)&a1l, g_a1lo);
    cudaGetSymbolAddress((void**)&aqh, g_aqhi);
    cudaGetSymbolAddress((void**)&aql, g_aqlo);
    cudaGetSymbolAddress((void**)&aoh, g_aohi);
    cudaGetSymbolAddress((void**)&aol, g_aolo);
    cudaGetSymbolAddress((void**)&qP,  g_qP);
    cudaGetSymbolAddress((void**)&oP,  g_oP);
    cudaGetSymbolAddress((void**)&cst, g_c);
    cudaGetSymbolAddress((void**)&bsum, g_bsum);

    const size_t LW = (size_t)2048 * 4096;  // per-layer weight elems
    dim3 tb(32, 8);
    // LSTM weights: k-major, gate-interleaved columns. k rows 0..1023 = input part, 1024..2047 = h part.
    for (int l = 0; l < 2; l++) {
        tsplit<<<dim3(32, 128), tb>>>(Wih + (size_t)l * 4096 * 1024,
            Whi + l * LW, Wlo + l * LW, 4096, 1024, 4096, 1);
        tsplit<<<dim3(32, 128), tb>>>(Whh + (size_t)l * 4096 * 1024,
            Whi + l * LW + (size_t)1024 * 4096, Wlo + l * LW + (size_t)1024 * 4096, 4096, 1024, 4096, 1);
    }
    tsplit<<<dim3(32, 32), tb>>>(W1, W1h, W1l, 1024, 1024, 1024, 0);
    tsplit<<<dim3(64, 16), tb>>>(W2, W2h, W2l, 512, 2048, 512, 0);
    bias_k<<<32, 256>>>(bih, bhh);
    embed_k<<<(TT * BB * EE + 255) / 256, 256>>>(tgt, emb);
    init_k<<<(BB * HH + 255) / 256, 256>>>(out0, hinit);
    // Precompute x-part of layer0 gates for all t: [4096][4096] = Xall @ Wx (k rows 0..511)
    gemm_split3<<<dim3(64, 1, 64), 256>>>(xh, xl, 512, Whi, Wlo, 4096, xp, 4096, 512);

    for (int t = 0; t < TT; t++) {
        const bf16* A0h = a0h + (size_t)t * BB * 1536;
        const bf16* A0l = a0l + (size_t)t * BB * 1536;
        bf16* nxHh = (t + 1 < TT) ? a0h + (size_t)(t + 1) * BB * 1536 + 512 : nullptr;
        bf16* nxHl = (t + 1 < TT) ? a0l + (size_t)(t + 1) * BB * 1536 + 512 : nullptr;
        bf16* nxOh = (t + 1 < TT) ? a0h + (size_t)(t + 1) * BB * 1536 : nullptr;
        bf16* nxOl = (t + 1 < TT) ? a0l + (size_t)(t + 1) * BB * 1536 : nullptr;

        // layer0 gates + cell (K per term = 1536: [out|h0]; x-part from xp)
        gemm_lstm<<<128, 256>>>(A0h, A0l, 1536, 1536,
                                Whi + (size_t)512 * 4096, Wlo + (size_t)512 * 4096,
                                xp + (size_t)t * BB * 4096, bsum, cst,
                                a1h, a1l, 2048, nxHh, nxHl, 1536, nullptr, nullptr, 0);
        // layer1 gates + cell (K per term = 2048: [h0|h1prev])
        gemm_lstm<<<128, 256>>>(a1h, a1l, 2048, 2048,
                                Whi + LW, Wlo + LW,
                                nullptr, bsum + 4096, cst + BB * HH,
                                a1h + 1024, a1l + 1024, 2048, aqh, aql, 1024,
                                aoh + 1024, aol + 1024, 2048);
        // q = h1 @ W1^T
        gemm_split3<<<dim3(16, 8, 1), 256>>>(aqh, aql, 1024, W1h, W1l, 1024, qP, 1024, 128);
        attn_k<<<64, 512>>>(qP, b1, enc, aoh, aol);
        // o = tanh([attended|h1] @ W2^T + b2)
        gemm_split3<<<dim3(8, 16, 1), 256>>>(aoh, aol, 2048, W2h, W2l, 512, oP, 512, 128);
        out_k<<<128, 256>>>(oP, b2, out, t, nxOh, nxOl);
    }
}

// round 6
// speedup vs baseline: 1.3426x; 1.3426x over previous
#include <cuda_runtime.h>
#include <cuda_bf16.h>
#include <cstdint>
#include <math.h>

using bf16 = __nv_bfloat16;

#define TT 64
#define BB 64
#define EE 512
#define HH 1024
#define SS 128
#define VV 1024
#define NBLK 128

// ---- persistent scratch (device globals; no allocation) ----
__device__ __align__(16) bf16 g_Whi[2][2048u*4096u];  // LSTM weights k-major [k][4096]
__device__ __align__(16) bf16 g_Wlo[2][2048u*4096u];
__device__ __align__(16) bf16 g_W1hi[1024u*1024u];
__device__ __align__(16) bf16 g_W1lo[1024u*1024u];
__device__ __align__(16) bf16 g_W2hi[2048u*512u];
__device__ __align__(16) bf16 g_W2lo[2048u*512u];
__device__ __align__(16) bf16 g_xhi[4096u*512u];      // all-t embeddings [t*64+b][512]
__device__ __align__(16) bf16 g_xlo[4096u*512u];
__device__ float g_xp[(size_t)4096*4096];             // x@Wx per (t,b) row
__device__ __align__(16) bf16 g_a0hi[BB*1536];        // layer0 input [out|h0]
__device__ __align__(16) bf16 g_a0lo[BB*1536];
__device__ __align__(16) bf16 g_a1hi[BB*2048];        // layer1 input [h0|h1prev]
__device__ __align__(16) bf16 g_a1lo[BB*2048];
__device__ __align__(16) bf16 g_aqhi[BB*1024];        // h1 for W1 gemm
__device__ __align__(16) bf16 g_aqlo[BB*1024];
__device__ __align__(16) bf16 g_aohi[BB*2048];        // [attended|h1]
__device__ __align__(16) bf16 g_aolo[BB*2048];
__device__ float g_gP[2][BB*4096];
__device__ float g_qP[8][BB*1024];
__device__ float g_oP[16][BB*512];
__device__ float g_sc[BB*SS];
__device__ float g_c[2][BB*1024];
__device__ unsigned g_bar;

// ---- helpers ----
__device__ __forceinline__ void splitbf(float x, bf16* h, bf16* l) {
    bf16 hi = __float2bfloat16(x);
    *h = hi;
    *l = __float2bfloat16(x - __bfloat162float(hi));
}

__device__ __forceinline__ void cp16(bf16* s, const bf16* g) {
    uint32_t sa = (uint32_t)__cvta_generic_to_shared(s);
    asm volatile("cp.async.cg.shared.global [%0], [%1], 16;" :: "r"(sa), "l"(g) : "memory");
}

union SMem {
    struct { bf16 As[2][64][64]; bf16 Bs[2][64][64]; } g;
    struct { float qs[1024]; float w[128]; } a;
};

// ---- grid barrier: monotonic counter, reset by memset before launch ----
__device__ __forceinline__ void gridbar(unsigned& gen) {
    __syncthreads();
    if (threadIdx.x == 0) {
        __threadfence();
        atomicAdd(&g_bar, 1u);
        gen += NBLK;
        while (*(volatile unsigned*)&g_bar < gen) { }
        __threadfence();
    }
    __syncthreads();
}

// ---- GEMM phase: C[64,N] partial (ks) = Ahi@Bhi + Alo@Bhi + Ahi@Blo ----
__device__ __forceinline__ void gemm_ph(SMem* sm,
    const bf16* __restrict__ Ahi, const bf16* __restrict__ Alo, int lda,
    const bf16* __restrict__ Bhi, const bf16* __restrict__ Blo, int ldb,
    float* __restrict__ Cp, int N, int Ksplit, int bx, int ks)
{
    const int tid = threadIdx.x, lane = tid & 31, wp = tid >> 5;
    const int wm = wp >> 2, wn = wp & 3;
    const int nb = bx * 64;
    const int k0 = ks * Ksplit;
    const int nk = Ksplit >> 6;
    const int iters = 3 * nk;
    const bf16* At[3] = {Ahi, Alo, Ahi};
    const bf16* Bt[3] = {Bhi, Bhi, Blo};

    float acc[2][2][4];
#pragma unroll
    for (int i = 0; i < 2; i++)
#pragma unroll
        for (int j = 0; j < 2; j++)
#pragma unroll
            for (int r = 0; r < 4; r++) acc[i][j][r] = 0.f;

    auto issue = [&](int it, int buf) {
        int term = it / nk;
        int kb = k0 + (it - term * nk) * 64;
        const bf16* Ag = At[term];
        const bf16* Bg = Bt[term];
#pragma unroll
        for (int r = 0; r < 2; r++) {
            int ch = tid + 256 * r, row = ch >> 3, c8 = ch & 7;
            cp16(&sm->g.As[buf][row][((c8 ^ (row & 7)) << 3)], Ag + (size_t)row * lda + kb + (c8 << 3));
            cp16(&sm->g.Bs[buf][row][((c8 ^ (row & 7)) << 3)], Bg + (size_t)(kb + row) * ldb + nb + (c8 << 3));
        }
        asm volatile("cp.async.commit_group;");
    };

    issue(0, 0);
    for (int it = 0; it < iters; ++it) {
        int buf = it & 1;
        if (it + 1 < iters) {
            issue(it + 1, buf ^ 1);
            asm volatile("cp.async.wait_group 1;");
        } else {
            asm volatile("cp.async.wait_group 0;");
        }
        __syncthreads();
#pragma unroll
        for (int kk = 0; kk < 4; kk++) {
            uint32_t a[2][4], b[2][2];
#pragma unroll
            for (int mi = 0; mi < 2; mi++) {
                int m = (wm << 5) + (mi << 4) + (lane & 15);
                int pc = ((kk << 1) + (lane >> 4)) ^ (m & 7);
                uint32_t ad = (uint32_t)__cvta_generic_to_shared(&sm->g.As[buf][m][pc << 3]);
                asm volatile("ldmatrix.sync.aligned.m8n8.x4.shared.b16 {%0,%1,%2,%3},[%4];"
                             : "=r"(a[mi][0]), "=r"(a[mi][1]), "=r"(a[mi][2]), "=r"(a[mi][3]) : "r"(ad));
            }
#pragma unroll
            for (int ni = 0; ni < 2; ni++) {
                int kr = (kk << 4) + (lane & 15);
                int pc = ((wn << 1) + ni) ^ (kr & 7);
                uint32_t ad = (uint32_t)__cvta_generic_to_shared(&sm->g.Bs[buf][kr][pc << 3]);
                asm volatile("ldmatrix.sync.aligned.m8n8.x2.trans.shared.b16 {%0,%1},[%2];"
                             : "=r"(b[ni][0]), "=r"(b[ni][1]) : "r"(ad));
            }
#pragma unroll
            for (int mi = 0; mi < 2; mi++)
#pragma unroll
                for (int ni = 0; ni < 2; ni++)
                    asm volatile(
                        "mma.sync.aligned.m16n8k16.row.col.f32.bf16.bf16.f32 "
                        "{%0,%1,%2,%3},{%4,%5,%6,%7},{%8,%9},{%0,%1,%2,%3};"
                        : "+f"(acc[mi][ni][0]), "+f"(acc[mi][ni][1]), "+f"(acc[mi][ni][2]), "+f"(acc[mi][ni][3])
                        : "r"(a[mi][0]), "r"(a[mi][1]), "r"(a[mi][2]), "r"(a[mi][3]),
                          "r"(b[ni][0]), "r"(b[ni][1]));
        }
        __syncthreads();
    }

    float* C = Cp + (size_t)ks * 64 * N;
#pragma unroll
    for (int mi = 0; mi < 2; mi++)
#pragma unroll
        for (int ni = 0; ni < 2; ni++) {
            int row = (wm << 5) + (mi << 4) + (lane >> 2);
            int col = nb + (wn << 4) + (ni << 3) + ((lane & 3) << 1);
            C[(size_t)row * N + col]           = acc[mi][ni][0];
            C[(size_t)row * N + col + 1]       = acc[mi][ni][1];
            C[(size_t)(row + 8) * N + col]     = acc[mi][ni][2];
            C[(size_t)(row + 8) * N + col + 1] = acc[mi][ni][3];
        }
}

// ---- LSTM cell phase ----
__device__ __forceinline__ void cell_ph(int bid, int tid,
    const float* __restrict__ xp, const float* __restrict__ bi, const float* __restrict__ bh,
    float* __restrict__ c,
    bf16* d0h, bf16* d0l, int s0, bf16* d1h, bf16* d1l, int s1,
    bf16* d2h, bf16* d2l, int s2)
{
#pragma unroll
    for (int r = 0; r < 2; r++) {
        int idx = bid * 512 + r * 256 + tid;
        int b = idx >> 10, j = idx & 1023;
        const float* p0 = g_gP[0] + (size_t)b * 4096;
        const float* p1 = g_gP[1] + (size_t)b * 4096;
        float gi = __ldcg(p0 + j)        + __ldcg(p1 + j)        + bi[j]        + bh[j];
        float gf = __ldcg(p0 + 1024 + j) + __ldcg(p1 + 1024 + j) + bi[1024 + j] + bh[1024 + j];
        float gg = __ldcg(p0 + 2048 + j) + __ldcg(p1 + 2048 + j) + bi[2048 + j] + bh[2048 + j];
        float go = __ldcg(p0 + 3072 + j) + __ldcg(p1 + 3072 + j) + bi[3072 + j] + bh[3072 + j];
        if (xp) {
            const float* xr = xp + (size_t)b * 4096;
            gi += __ldcg(xr + j); gf += __ldcg(xr + 1024 + j);
            gg += __ldcg(xr + 2048 + j); go += __ldcg(xr + 3072 + j);
        }
        float si = 1.f / (1.f + expf(-gi));
        float sf = 1.f / (1.f + expf(-gf));
        float so = 1.f / (1.f + expf(-go));
        float cn = sf * c[idx] + si * tanhf(gg);
        c[idx] = cn;
        float h = so * tanhf(cn);
        bf16 hi, lo;
        splitbf(h, &hi, &lo);
        d0h[(size_t)b * s0 + j] = hi; d0l[(size_t)b * s0 + j] = lo;
        d1h[(size_t)b * s1 + j] = hi; d1l[(size_t)b * s1 + j] = lo;
        if (d2h) { d2h[(size_t)b * s2 + j] = hi; d2l[(size_t)b * s2 + j] = lo; }
    }
}

// ---- megakernel: whole decode loop ----
__global__ __launch_bounds__(256, 1) void mega(
    const float* __restrict__ enc,
    const float* __restrict__ bih, const float* __restrict__ bhh,
    const float* __restrict__ b1, const float* __restrict__ b2,
    float* __restrict__ out)
{
    __shared__ SMem sm;
    const int bid = blockIdx.x, tid = threadIdx.x;
    const int lane = tid & 31, wp = tid >> 5;
    unsigned gen = 0;

    for (int t = 0; t < TT; t++) {
        // L0 gates: A=[out|h0] K=1536, weights rows 512..2047 of layer0
        gemm_ph(&sm, g_a0hi, g_a0lo, 1536,
                g_Whi[0] + (size_t)512 * 4096, g_Wlo[0] + (size_t)512 * 4096, 4096,
                g_gP[0], 4096, 768, bid & 63, bid >> 6);
        gridbar(gen);
        cell_ph(bid, tid, g_xp + (size_t)t * BB * 4096, bih, bhh, g_c[0],
                g_a1hi, g_a1lo, 2048,                   // a1 slot0 = h0
                g_a0hi + 512, g_a0lo + 512, 1536,       // a0 h0-slot (next step)
                nullptr, nullptr, 0);
        gridbar(gen);
        // L1 gates: A=[h0|h1prev] K=2048
        gemm_ph(&sm, g_a1hi, g_a1lo, 2048, g_Whi[1], g_Wlo[1], 4096,
                g_gP[0], 4096, 1024, bid & 63, bid >> 6);
        gridbar(gen);
        cell_ph(bid, tid, nullptr, bih + 4096, bhh + 4096, g_c[1],
                g_a1hi + 1024, g_a1lo + 1024, 2048,     // a1 slot1 = h1prev
                g_aqhi, g_aqlo, 1024,                   // q-gemm input
                g_aohi + 1024, g_aolo + 1024, 2048);    // ao slot1 = h1
        gridbar(gen);
        // q = h1 @ W1^T
        gemm_ph(&sm, g_aqhi, g_aqlo, 1024, g_W1hi, g_W1lo, 1024,
                g_qP[0], 1024, 128, bid & 15, bid >> 4);
        gridbar(gen);
        // attention scores: 2 blocks per batch, each 64 s-rows
        {
            int b = bid >> 1, half = bid & 1;
            for (int v = tid; v < 1024; v += 256) {
                float s = b1[v];
#pragma unroll
                for (int p = 0; p < 8; p++) s += __ldcg(&g_qP[p][(size_t)b * 1024 + v]);
                sm.a.qs[v] = s;
            }
            __syncthreads();
            const float* eb = enc + (size_t)b * SS * VV;
            const float4* q4 = (const float4*)sm.a.qs;
            for (int sl = wp; sl < 64; sl += 8) {
                int s = half * 64 + sl;
                const float4* e4 = (const float4*)(eb + (size_t)s * VV);
                float acc = 0.f;
#pragma unroll 2
                for (int i = lane; i < 256; i += 32) {
                    float4 ev = e4[i], qv = q4[i];
                    acc += qv.x * ev.x + qv.y * ev.y + qv.z * ev.z + qv.w * ev.w;
                }
#pragma unroll
                for (int o = 16; o > 0; o >>= 1) acc += __shfl_xor_sync(0xffffffffu, acc, o);
                if (lane == 0) g_sc[b * SS + s] = acc;
            }
        }
        gridbar(gen);
        // softmax + attended: 2 blocks per batch, each 512 v-cols
        {
            int b = bid >> 1, half = bid & 1;
            if (wp == 0) {
                float v[4], m = -1e30f;
#pragma unroll
                for (int i = 0; i < 4; i++) { v[i] = __ldcg(&g_sc[b * SS + lane + 32 * i]); m = fmaxf(m, v[i]); }
#pragma unroll
                for (int o = 16; o > 0; o >>= 1) m = fmaxf(m, __shfl_xor_sync(0xffffffffu, m, o));
                float sum = 0.f;
#pragma unroll
                for (int i = 0; i < 4; i++) { v[i] = expf(v[i] - m); sum += v[i]; }
#pragma unroll
                for (int o = 16; o > 0; o >>= 1) sum += __shfl_xor_sync(0xffffffffu, sum, o);
                float inv = 1.f / sum;
#pragma unroll
                for (int i = 0; i < 4; i++) sm.a.w[lane + 32 * i] = v[i] * inv;
            }
            __syncthreads();
            const float* eb = enc + (size_t)b * SS * VV;
            int col = half * 512 + 2 * tid;
            float a0 = 0.f, a1 = 0.f;
#pragma unroll 4
            for (int s = 0; s < SS; s++) {
                float wt = sm.a.w[s];
                float2 ev = *(const float2*)(eb + (size_t)s * VV + col);
                a0 += wt * ev.x; a1 += wt * ev.y;
            }
            bf16 hi, lo;
            splitbf(a0, &hi, &lo);
            g_aohi[(size_t)b * 2048 + col] = hi; g_aolo[(size_t)b * 2048 + col] = lo;
            splitbf(a1, &hi, &lo);
            g_aohi[(size_t)b * 2048 + col + 1] = hi; g_aolo[(size_t)b * 2048 + col + 1] = lo;
        }
        gridbar(gen);
        // o = [attended|h1] @ W2^T
        gemm_ph(&sm, g_aohi, g_aolo, 2048, g_W2hi, g_W2lo, 512,
                g_oP[0], 512, 128, bid & 7, bid >> 3);
        gridbar(gen);
        // out: combine + tanh -> d_out + input-feed slot
        {
            int idx = bid * 256 + tid;   // 64*512
            int b = idx >> 9, e = idx & 511;
            float s = b2[e];
#pragma unroll
            for (int p = 0; p < 16; p++) s += __ldcg(&g_oP[p][idx]);
            float o = tanhf(s);
            out[((size_t)b * TT + t) * EE + e] = o;
            bf16 hi, lo;
            splitbf(o, &hi, &lo);
            g_a0hi[(size_t)b * 1536 + e] = hi;
            g_a0lo[(size_t)b * 1536 + e] = lo;
        }
        gridbar(gen);
    }
}

// ---- standalone GEMM for x-precompute (grid: N/64 x 1 x M/64) ----
__global__ __launch_bounds__(256, 2) void gemm_pre(
    const bf16* __restrict__ Ahi, const bf16* __restrict__ Alo, int lda,
    const bf16* __restrict__ Bhi, const bf16* __restrict__ Blo, int ldb,
    float* __restrict__ Cp, int N, int Ksplit)
{
    __shared__ SMem sm;
    const size_t rowOff = (size_t)blockIdx.z * 64;
    gemm_ph(&sm, Ahi + rowOff * lda, Alo + rowOff * lda, lda, Bhi, Blo, ldb,
            Cp + (size_t)blockIdx.z * 64 * N, N, Ksplit, blockIdx.x, 0);
}

// ---- transpose + split fp32 [R][C] -> bf16 hi/lo [C][R] ----
__global__ void tsplit(const float* __restrict__ src, bf16* __restrict__ dhi,
                       bf16* __restrict__ dlo, int C, int ldd)
{
    __shared__ float t[32][33];
    int kb = blockIdx.x << 5, nbs = blockIdx.y << 5;
    int tx = threadIdx.x, ty = threadIdx.y;  // 32x8
    for (int i = ty; i < 32; i += 8) t[i][tx] = src[(size_t)(nbs + i) * C + kb + tx];
    __syncthreads();
    for (int i = ty; i < 32; i += 8) {
        float v = t[tx][i];
        size_t o = (size_t)(kb + i) * ldd + nbs + tx;
        bf16 hi, lo;
        splitbf(v, &hi, &lo);
        dhi[o] = hi; dlo[o] = lo;
    }
}

// ---- embed all timesteps ----
__global__ void embed_k(const int* __restrict__ tgt, const float* __restrict__ emb)
{
    int idx = blockIdx.x * blockDim.x + threadIdx.x;
    if (idx >= TT * BB * EE) return;
    int e = idx & 511, tb = idx >> 9;
    int b = tb & 63, t = tb >> 6;
    int tok = tgt[t * BB + b];
    float v = emb[(size_t)tok * EE + e];
    size_t o = ((size_t)t * BB + b) * 512 + e;
    bf16 hi, lo;
    splitbf(v, &hi, &lo);
    g_xhi[o] = hi; g_xlo[o] = lo;
}

// ---- init state ----
__global__ void init_k(const float* __restrict__ out0, const float* __restrict__ hinit)
{
    int idx = blockIdx.x * blockDim.x + threadIdx.x;
    if (idx >= BB * HH) return;
    int b = idx >> 10, j = idx & 1023;
    g_c[0][idx] = 0.f; g_c[1][idx] = 0.f;
    bf16 hi, lo;
    splitbf(hinit[(size_t)BB * HH + idx], &hi, &lo);  // layer1 h init -> a1 slot1
    g_a1hi[(size_t)b * 2048 + 1024 + j] = hi;
    g_a1lo[(size_t)b * 2048 + 1024 + j] = lo;
    splitbf(hinit[idx], &hi, &lo);                    // layer0 h init -> a0 h0-slot
    g_a0hi[(size_t)b * 1536 + 512 + j] = hi;
    g_a0lo[(size_t)b * 1536 + 512 + j] = lo;
    if (j < 512) {
        splitbf(out0[(size_t)b * EE + j], &hi, &lo);  // input feed init
        g_a0hi[(size_t)b * 1536 + j] = hi;
        g_a0lo[(size_t)b * 1536 + j] = lo;
    }
}

extern "C" void kernel_launch(void* const* d_in, const int* in_sizes, int n_in,
                              void* d_out, int out_size)
{
    const int*   tgt   = (const int*)d_in[0];
    const float* enc   = (const float*)d_in[1];
    const float* emb   = (const float*)d_in[2];
    const float* out0  = (const float*)d_in[3];
    const float* hinit = (const float*)d_in[4];
    const float* Wih   = (const float*)d_in[5];
    const float* Whh   = (const float*)d_in[6];
    const float* bih   = (const float*)d_in[7];
    const float* bhh   = (const float*)d_in[8];
    const float* W1    = (const float*)d_in[9];
    const float* b1    = (const float*)d_in[10];
    const float* W2    = (const float*)d_in[11];
    const float* b2    = (const float*)d_in[12];
    float* out = (float*)d_out;

    bf16 *Whi, *Wlo, *W1h, *W1l, *W2h, *W2l, *xh, *xl;
    float *xp;
    void* barp;
    cudaGetSymbolAddress((void**)&Whi, g_Whi);
    cudaGetSymbolAddress((void**)&Wlo, g_Wlo);
    cudaGetSymbolAddress((void**)&W1h, g_W1hi);
    cudaGetSymbolAddress((void**)&W1l, g_W1lo);
    cudaGetSymbolAddress((void**)&W2h, g_W2hi);
    cudaGetSymbolAddress((void**)&W2l, g_W2lo);
    cudaGetSymbolAddress((void**)&xh,  g_xhi);
    cudaGetSymbolAddress((void**)&xl,  g_xlo);
    cudaGetSymbolAddress((void**)&xp,  g_xp);
    cudaGetSymbolAddress(&barp, g_bar);

    const size_t LW = (size_t)2048 * 4096;
    dim3 tb(32, 8);
    // LSTM weights -> k-major: rows 0..1023 = Wih^T, 1024..2047 = Whh^T
    for (int l = 0; l < 2; l++) {
        tsplit<<<dim3(32, 128), tb>>>(Wih + (size_t)l * 4096 * 1024,
            Whi + l * LW, Wlo + l * LW, 1024, 4096);
        tsplit<<<dim3(32, 128), tb>>>(Whh + (size_t)l * 4096 * 1024,
            Whi + l * LW + (size_t)1024 * 4096, Wlo + l * LW + (size_t)1024 * 4096, 1024, 4096);
    }
    tsplit<<<dim3(32, 32), tb>>>(W1, W1h, W1l, 1024, 1024);
    tsplit<<<dim3(64, 16), tb>>>(W2, W2h, W2l, 2048, 512);
    embed_k<<<(TT * BB * EE + 255) / 256, 256>>>(tgt, emb);
    init_k<<<(BB * HH + 255) / 256, 256>>>(out0, hinit);
    // Precompute x-part of layer0 gates for all (t,b): rows of Xall vs weight rows 0..511
    gemm_pre<<<dim3(64, 1, 64), 256>>>(xh, xl, 512, Whi, Wlo, 4096, xp, 4096, 512);

    cudaMemsetAsync(barp, 0, sizeof(unsigned));
    mega<<<NBLK, 256>>>(enc, bih, bhh, b1, b2, out);
}

// round 8
// speedup vs baseline: 2.0140x; 1.5001x over previous
#include <cuda_runtime.h>
#include <cuda_bf16.h>
#include <cstdint>
#include <math.h>

using bf16 = __nv_bfloat16;

#define TT 64
#define BB 64
#define EE 512
#define HH 1024
#define SS 128
#define VV 1024
#define NBLK 128

// swizzled offset inside a 64x64 bf16 tile (row r, col c)
#define SW(r,c) ((r)*64 + ((((c)>>3) ^ ((r)&7))<<3) + ((c)&7))

// ---- dynamic smem layout (bytes) ----
#define SM_MBAR 0
#define SM_GEMM 128          // 2 bufs x 4 planes x 8KB = 64KB
#define SM_QS   65664        // 4KB floats
#define SM_W    69760        // 512B
#define SM_ENC  70400        // 2 bufs x 32KB
#define SM_TOTAL 135936
#define SM_PRE_TOTAL 65664

// ---- persistent scratch (device globals; no allocation) ----
__device__ __align__(16) bf16 g_WLhi[2][(size_t)64*32*4096];  // LSTM weights, tile strips [ntile][32][4096]
__device__ __align__(16) bf16 g_WLlo[2][(size_t)64*32*4096];
__device__ __align__(16) bf16 g_Wqhi[(size_t)16*16*4096];     // W1 strips
__device__ __align__(16) bf16 g_Wqlo[(size_t)16*16*4096];
__device__ __align__(16) bf16 g_W2hi[(size_t)8*32*4096];      // W2 strips
__device__ __align__(16) bf16 g_W2lo[(size_t)8*32*4096];
__device__ __align__(16) bf16 g_xthi[(size_t)64*8*4096];      // embeddings tiles [t][8][4096]
__device__ __align__(16) bf16 g_xtlo[(size_t)64*8*4096];
__device__ float g_xp[(size_t)64*64*4096];                    // x@Wx per t: [t][b][4096]
__device__ __align__(16) bf16 g_a0hi[24*4096];                // [out(8)|h0(16)] tiles
__device__ __align__(16) bf16 g_a0lo[24*4096];
__device__ __align__(16) bf16 g_a1hi[32*4096];                // [h0(16)|h1prev(16)]
__device__ __align__(16) bf16 g_a1lo[32*4096];
__device__ __align__(16) bf16 g_aqhi[16*4096];                // h1
__device__ __align__(16) bf16 g_aqlo[16*4096];
__device__ __align__(16) bf16 g_aohi[32*4096];                // [attended(16)|h1(16)]
__device__ __align__(16) bf16 g_aolo[32*4096];
__device__ float g_gP[2*BB*4096];
__device__ float g_qP[8*BB*1024];
__device__ float g_oP[16*BB*512];
__device__ float g_sc[BB*SS];
__device__ float g_c[2*BB*1024];
__device__ unsigned g_bar;

// ---- helpers ----
__device__ __forceinline__ void splitbf(float x, bf16* h, bf16* l) {
    bf16 hi = __float2bfloat16(x);
    *h = hi;
    *l = __float2bfloat16(x - __bfloat162float(hi));
}

__device__ __forceinline__ void awr(bf16* dh, bf16* dl, int chunkBase, int b, int j, float v) {
    size_t off = (size_t)(chunkBase + (j >> 6)) * 4096 + SW(b, j & 63);
    bf16 hi, lo;
    splitbf(v, &hi, &lo);
    dh[off] = hi; dl[off] = lo;
}

__device__ __forceinline__ void mbinit(uint32_t bar) {
    asm volatile("mbarrier.init.shared.b64 [%0], %1;" :: "r"(bar), "r"(1u) : "memory");
}
__device__ __forceinline__ void mexpect(uint32_t bar, uint32_t bytes) {
    asm volatile("mbarrier.arrive.expect_tx.shared.b64 _, [%0], %1;" :: "r"(bar), "r"(bytes) : "memory");
}
__device__ __forceinline__ void mwait(uint32_t bar, uint32_t parity) {
    asm volatile("{\n\t.reg .pred P;\n"
        "W%=:\n\tmbarrier.try_wait.parity.shared.b64 P, [%0], %1;\n"
        "\t@P bra D%=;\n\tbra W%=;\nD%=:\n\t}"
        :: "r"(bar), "r"(parity) : "memory");
}
__device__ __forceinline__ void bulkcp(uint32_t dst, const void* src, uint32_t bytes, uint32_t bar) {
    asm volatile("cp.async.bulk.shared::cluster.global.mbarrier::complete_tx::bytes [%0], [%1], %2, [%3];"
        :: "r"(dst), "l"(src), "r"(bytes), "r"(bar) : "memory");
}

// ---- grid barrier ----
__device__ __forceinline__ void gridbar(unsigned& gen) {
    __syncthreads();
    if (threadIdx.x == 0) {
        __threadfence();
        atomicAdd(&g_bar, 1u);
        gen += NBLK;
        while (*(volatile unsigned*)&g_bar < gen) { }
        __threadfence();
    }
    __syncthreads();
}

// ---- GEMM with bulk tile loads. A/B strips are chunk-major 4096-elem swizzled tiles. ----
__device__ __forceinline__ void gemm_bulk(char* dsm,
    const bf16* __restrict__ Ahi, const bf16* __restrict__ Alo,
    const bf16* __restrict__ Bhi, const bf16* __restrict__ Blo,
    int nk, float* __restrict__ Cp, int N, int nb, unsigned* pc)
{
    const int tid = threadIdx.x, lane = tid & 31, wp = tid >> 5;
    const int wm = wp >> 2, wn = wp & 3;
    bf16* bufs = (bf16*)(dsm + SM_GEMM);
    uint32_t mb0 = (uint32_t)__cvta_generic_to_shared(dsm + SM_MBAR);
    uint32_t bufSm = (uint32_t)__cvta_generic_to_shared(bufs);

    float acc[2][2][4];
#pragma unroll
    for (int i = 0; i < 2; i++)
#pragma unroll
        for (int j = 0; j < 2; j++)
#pragma unroll
            for (int r = 0; r < 4; r++) acc[i][j][r] = 0.f;

    auto issue = [&](int ch, int buf) {
        if (tid == 0) {
            uint32_t bar = mb0 + buf * 8;
            mexpect(bar, 32768u);
            uint32_t d = bufSm + buf * 32768;
            bulkcp(d,         Ahi + (size_t)ch * 4096, 8192, bar);
            bulkcp(d + 8192,  Alo + (size_t)ch * 4096, 8192, bar);
            bulkcp(d + 16384, Bhi + (size_t)ch * 4096, 8192, bar);
            bulkcp(d + 24576, Blo + (size_t)ch * 4096, 8192, bar);
        }
    };

    issue(0, 0);
    for (int it = 0; it < nk; ++it) {
        int buf = it & 1;
        if (it + 1 < nk) issue(it + 1, buf ^ 1);
        mwait(mb0 + buf * 8, pc[buf] & 1);
        pc[buf]++;
        const bf16* AH = bufs + buf * 16384;
        const bf16* AL = AH + 4096;
        const bf16* BH = AH + 8192;
        const bf16* BL = AH + 12288;
#pragma unroll
        for (int kk = 0; kk < 4; kk++) {
            uint32_t ah[2][4], al[2][4], bh[2][2], bl[2][2];
#pragma unroll
            for (int mi = 0; mi < 2; mi++) {
                int m = (wm << 5) + (mi << 4) + (lane & 15);
                int pcn = ((kk << 1) + (lane >> 4)) ^ (m & 7);
                uint32_t adH = (uint32_t)__cvta_generic_to_shared(AH + m * 64 + (pcn << 3));
                asm volatile("ldmatrix.sync.aligned.m8n8.x4.shared.b16 {%0,%1,%2,%3},[%4];"
                             : "=r"(ah[mi][0]), "=r"(ah[mi][1]), "=r"(ah[mi][2]), "=r"(ah[mi][3]) : "r"(adH));
                uint32_t adL = (uint32_t)__cvta_generic_to_shared(AL + m * 64 + (pcn << 3));
                asm volatile("ldmatrix.sync.aligned.m8n8.x4.shared.b16 {%0,%1,%2,%3},[%4];"
                             : "=r"(al[mi][0]), "=r"(al[mi][1]), "=r"(al[mi][2]), "=r"(al[mi][3]) : "r"(adL));
            }
#pragma unroll
            for (int ni = 0; ni < 2; ni++) {
                int kr = (kk << 4) + (lane & 15);
                int pcn = ((wn << 1) + ni) ^ (kr & 7);
                uint32_t adH = (uint32_t)__cvta_generic_to_shared(BH + kr * 64 + (pcn << 3));
                asm volatile("ldmatrix.sync.aligned.m8n8.x2.trans.shared.b16 {%0,%1},[%2];"
                             : "=r"(bh[ni][0]), "=r"(bh[ni][1]) : "r"(adH));
                uint32_t adL = (uint32_t)__cvta_generic_to_shared(BL + kr * 64 + (pcn << 3));
                asm volatile("ldmatrix.sync.aligned.m8n8.x2.trans.shared.b16 {%0,%1},[%2];"
                             : "=r"(bl[ni][0]), "=r"(bl[ni][1]) : "r"(adL));
            }
#pragma unroll
            for (int mi = 0; mi < 2; mi++)
#pragma unroll
                for (int ni = 0; ni < 2; ni++) {
                    asm volatile("mma.sync.aligned.m16n8k16.row.col.f32.bf16.bf16.f32 "
                        "{%0,%1,%2,%3},{%4,%5,%6,%7},{%8,%9},{%0,%1,%2,%3};"
                        : "+f"(acc[mi][ni][0]), "+f"(acc[mi][ni][1]), "+f"(acc[mi][ni][2]), "+f"(acc[mi][ni][3])
                        : "r"(ah[mi][0]), "r"(ah[mi][1]), "r"(ah[mi][2]), "r"(ah[mi][3]),
                          "r"(bh[ni][0]), "r"(bh[ni][1]));
                    asm volatile("mma.sync.aligned.m16n8k16.row.col.f32.bf16.bf16.f32 "
                        "{%0,%1,%2,%3},{%4,%5,%6,%7},{%8,%9},{%0,%1,%2,%3};"
                        : "+f"(acc[mi][ni][0]), "+f"(acc[mi][ni][1]), "+f"(acc[mi][ni][2]), "+f"(acc[mi][ni][3])
                        : "r"(al[mi][0]), "r"(al[mi][1]), "r"(al[mi][2]), "r"(al[mi][3]),
                          "r"(bh[ni][0]), "r"(bh[ni][1]));
                    asm volatile("mma.sync.aligned.m16n8k16.row.col.f32.bf16.bf16.f32 "
                        "{%0,%1,%2,%3},{%4,%5,%6,%7},{%8,%9},{%0,%1,%2,%3};"
                        : "+f"(acc[mi][ni][0]), "+f"(acc[mi][ni][1]), "+f"(acc[mi][ni][2]), "+f"(acc[mi][ni][3])
                        : "r"(ah[mi][0]), "r"(ah[mi][1]), "r"(ah[mi][2]), "r"(ah[mi][3]),
                          "r"(bl[ni][0]), "r"(bl[ni][1]));
                }
        }
        __syncthreads();
    }

#pragma unroll
    for (int mi = 0; mi < 2; mi++)
#pragma unroll
        for (int ni = 0; ni < 2; ni++) {
            int row = (wm << 5) + (mi << 4) + (lane >> 2);
            int col = nb + (wn << 4) + (ni << 3) + ((lane & 3) << 1);
            *(float2*)(Cp + (size_t)row * N + col)       = make_float2(acc[mi][ni][0], acc[mi][ni][1]);
            *(float2*)(Cp + (size_t)(row + 8) * N + col) = make_float2(acc[mi][ni][2], acc[mi][ni][3]);
        }
}

// ---- LSTM cell phase ----
__device__ __forceinline__ void cell_ph(int bid, int tid,
    const float* __restrict__ xp, const float* __restrict__ bi, const float* __restrict__ bh,
    float* __restrict__ c, int which)  // which: 0=layer0, 1=layer1
{
#pragma unroll
    for (int r = 0; r < 2; r++) {
        int idx = bid * 512 + r * 256 + tid;
        int b = idx >> 10, j = idx & 1023;
        const float* p0 = g_gP + (size_t)b * 4096;
        const float* p1 = g_gP + (size_t)(BB + b) * 4096;
        float gi = __ldcg(p0 + j)        + __ldcg(p1 + j)        + bi[j]        + bh[j];
        float gf = __ldcg(p0 + 1024 + j) + __ldcg(p1 + 1024 + j) + bi[1024 + j] + bh[1024 + j];
        float gg = __ldcg(p0 + 2048 + j) + __ldcg(p1 + 2048 + j) + bi[2048 + j] + bh[2048 + j];
        float go = __ldcg(p0 + 3072 + j) + __ldcg(p1 + 3072 + j) + bi[3072 + j] + bh[3072 + j];
        if (xp) {
            const float* xr = xp + (size_t)b * 4096;
            gi += __ldcg(xr + j); gf += __ldcg(xr + 1024 + j);
            gg += __ldcg(xr + 2048 + j); go += __ldcg(xr + 3072 + j);
        }
        float si = 1.f / (1.f + expf(-gi));
        float sf = 1.f / (1.f + expf(-gf));
        float so = 1.f / (1.f + expf(-go));
        float cn = sf * c[idx] + si * tanhf(gg);
        c[idx] = cn;
        float h = so * tanhf(cn);
        bf16 hi, lo;
        splitbf(h, &hi, &lo);
        if (which == 0) {
            size_t o1 = (size_t)(j >> 6) * 4096 + SW(b, j & 63);
            g_a1hi[o1] = hi; g_a1lo[o1] = lo;
            size_t o0 = (size_t)(8 + (j >> 6)) * 4096 + SW(b, j & 63);
            g_a0hi[o0] = hi; g_a0lo[o0] = lo;
        } else {
            size_t sw = SW(b, j & 63);
            size_t o1 = (size_t)(16 + (j >> 6)) * 4096 + sw;
            g_a1hi[o1] = hi; g_a1lo[o1] = lo;
            size_t oq = (size_t)(j >> 6) * 4096 + sw;
            g_aqhi[oq] = hi; g_aqlo[oq] = lo;
            g_aohi[o1] = hi; g_aolo[o1] = lo;
        }
    }
}

// ---- megakernel ----
__global__ __launch_bounds__(256, 1) void mega(
    const float* __restrict__ enc,
    const float* __restrict__ bih, const float* __restrict__ bhh,
    const float* __restrict__ b1, const float* __restrict__ b2,
    float* __restrict__ out)
{
    extern __shared__ char dsm[];
    const int bid = blockIdx.x, tid = threadIdx.x;
    const int lane = tid & 31, wp = tid >> 5;
    unsigned gen = 0;
    unsigned pc[4] = {0, 0, 0, 0};

    uint32_t mb0 = (uint32_t)__cvta_generic_to_shared(dsm + SM_MBAR);
    if (tid == 0) {
        mbinit(mb0); mbinit(mb0 + 8); mbinit(mb0 + 16); mbinit(mb0 + 24);
        asm volatile("fence.proxy.async.shared::cta;" ::: "memory");
    }
    __syncthreads();

    float* qs = (float*)(dsm + SM_QS);
    float* wsm = (float*)(dsm + SM_W);
    float* encS = (float*)(dsm + SM_ENC);
    uint32_t encSm = (uint32_t)__cvta_generic_to_shared(encS);

    for (int t = 0; t < TT; t++) {
        int bx = bid & 63, ks = bid >> 6;
        // L0 gates: A chunks ks*12..+12 of a0, B chunks 8+ks*12 of W0 strip
        gemm_bulk(dsm,
                  g_a0hi + (size_t)ks * 12 * 4096, g_a0lo + (size_t)ks * 12 * 4096,
                  g_WLhi[0] + ((size_t)bx * 32 + 8 + ks * 12) * 4096,
                  g_WLlo[0] + ((size_t)bx * 32 + 8 + ks * 12) * 4096,
                  12, g_gP + (size_t)ks * BB * 4096, 4096, bx * 64, pc);
        gridbar(gen);
        cell_ph(bid, tid, g_xp + (size_t)t * BB * 4096, bih, bhh, g_c, 0);
        gridbar(gen);
        // L1 gates
        gemm_bulk(dsm,
                  g_a1hi + (size_t)ks * 16 * 4096, g_a1lo + (size_t)ks * 16 * 4096,
                  g_WLhi[1] + ((size_t)bx * 32 + ks * 16) * 4096,
                  g_WLlo[1] + ((size_t)bx * 32 + ks * 16) * 4096,
                  16, g_gP + (size_t)ks * BB * 4096, 4096, bx * 64, pc);
        gridbar(gen);
        cell_ph(bid, tid, nullptr, bih + 4096, bhh + 4096, g_c + BB * HH, 1);
        gridbar(gen);
        // q = h1 @ W1^T : 16 ntiles x 8 splits
        {
            int qbx = bid & 15, qks = bid >> 4;
            gemm_bulk(dsm,
                      g_aqhi + (size_t)qks * 2 * 4096, g_aqlo + (size_t)qks * 2 * 4096,
                      g_Wqhi + ((size_t)qbx * 16 + qks * 2) * 4096,
                      g_Wqlo + ((size_t)qbx * 16 + qks * 2) * 4096,
                      2, g_qP + (size_t)qks * BB * 1024, 1024, qbx * 64, pc);
        }
        gridbar(gen);
        // attention scores: 2 blocks/batch, 64 rows each, bulk-staged
        {
            int b = bid >> 1, half = bid & 1;
            for (int v = tid; v < 1024; v += 256) {
                float s = b1[v];
#pragma unroll
                for (int p = 0; p < 8; p++) s += __ldcg(g_qP + (size_t)p * BB * 1024 + (size_t)b * 1024 + v);
                qs[v] = s;
            }
            __syncthreads();
            const float* eb = enc + (size_t)b * SS * VV;
            auto issueS = [&](int ch, int buf) {
                if (tid == 0) {
                    uint32_t bar = mb0 + 16 + buf * 8;
                    mexpect(bar, 32768u);
                    bulkcp(encSm + buf * 32768, eb + (size_t)(half * 64 + ch * 8) * 1024, 32768, bar);
                }
            };
            issueS(0, 0);
            for (int ch = 0; ch < 8; ch++) {
                int buf = ch & 1;
                if (ch + 1 < 8) issueS(ch + 1, buf ^ 1);
                mwait(mb0 + 16 + buf * 8, pc[2 + buf] & 1);
                pc[2 + buf]++;
                const float4* e4 = (const float4*)(encS + buf * 8192 + wp * 1024);
                const float4* q4 = (const float4*)qs;
                float acc = 0.f;
#pragma unroll 2
                for (int i = lane; i < 256; i += 32) {
                    float4 ev = e4[i], qv = q4[i];
                    acc += qv.x * ev.x + qv.y * ev.y + qv.z * ev.z + qv.w * ev.w;
                }
#pragma unroll
                for (int o = 16; o > 0; o >>= 1) acc += __shfl_xor_sync(0xffffffffu, acc, o);
                if (lane == 0) g_sc[b * SS + half * 64 + ch * 8 + wp] = acc;
                __syncthreads();
            }
        }
        gridbar(gen);
        // softmax + attended: 2 blocks/batch, 512 cols each, bulk-staged
        {
            int b = bid >> 1, half = bid & 1;
            if (wp == 0) {
                float v[4], m = -1e30f;
#pragma unroll
                for (int i = 0; i < 4; i++) { v[i] = __ldcg(g_sc + b * SS + lane + 32 * i); m = fmaxf(m, v[i]); }
#pragma unroll
                for (int o = 16; o > 0; o >>= 1) m = fmaxf(m, __shfl_xor_sync(0xffffffffu, m, o));
                float sum = 0.f;
#pragma unroll
                for (int i = 0; i < 4; i++) { v[i] = expf(v[i] - m); sum += v[i]; }
#pragma unroll
                for (int o = 16; o > 0; o >>= 1) sum += __shfl_xor_sync(0xffffffffu, sum, o);
                float inv = 1.f / sum;
#pragma unroll
                for (int i = 0; i < 4; i++) wsm[lane + 32 * i] = v[i] * inv;
            }
            __syncthreads();
            const float* eb = enc + (size_t)b * SS * VV + half * 512;
            auto issueA = [&](int ch, int buf) {
                if (tid == 0) {
                    uint32_t bar = mb0 + 16 + buf * 8;
                    mexpect(bar, 32768u);
#pragma unroll
                    for (int r = 0; r < 16; r++)
                        bulkcp(encSm + buf * 32768 + r * 2048, eb + (size_t)(ch * 16 + r) * 1024, 2048, bar);
                }
            };
            float a0 = 0.f, a1 = 0.f;
            issueA(0, 0);
            for (int ch = 0; ch < 8; ch++) {
                int buf = ch & 1;
                if (ch + 1 < 8) issueA(ch + 1, buf ^ 1);
                mwait(mb0 + 16 + buf * 8, pc[2 + buf] & 1);
                pc[2 + buf]++;
                const float* ebuf = encS + buf * 8192;
#pragma unroll 4
                for (int r = 0; r < 16; r++) {
                    float wt = wsm[ch * 16 + r];
                    float2 ev = *(const float2*)(ebuf + r * 512 + 2 * tid);
                    a0 += wt * ev.x; a1 += wt * ev.y;
                }
                __syncthreads();
            }
            int col = half * 512 + 2 * tid;
            awr(g_aohi, g_aolo, 0, b, col, a0);
            awr(g_aohi, g_aolo, 0, b, col + 1, a1);
        }
        gridbar(gen);
        // o = [attended|h1] @ W2^T : 8 ntiles x 16 splits
        {
            int obx = bid & 7, oks = bid >> 3;
            gemm_bulk(dsm,
                      g_aohi + (size_t)oks * 2 * 4096, g_aolo + (size_t)oks * 2 * 4096,
                      g_W2hi + ((size_t)obx * 32 + oks * 2) * 4096,
                      g_W2lo + ((size_t)obx * 32 + oks * 2) * 4096,
                      2, g_oP + (size_t)oks * BB * 512, 512, obx * 64, pc);
        }
        gridbar(gen);
        // out: combine + tanh -> d_out + input-feed slot
        {
            int idx = bid * 256 + tid;
            int b = idx >> 9, e = idx & 511;
            float s = b2[e];
#pragma unroll
            for (int p = 0; p < 16; p++) s += __ldcg(g_oP + (size_t)p * BB * 512 + idx);
            float o = tanhf(s);
            out[((size_t)b * TT + t) * EE + e] = o;
            awr(g_a0hi, g_a0lo, 0, b, e, o);
        }
        gridbar(gen);
    }
}

// ---- x-precompute GEMM: grid (64 ntile, 64 t) ----
__global__ __launch_bounds__(256, 2) void gemm_pre()
{
    extern __shared__ char dsm[];
    uint32_t mb0 = (uint32_t)__cvta_generic_to_shared(dsm + SM_MBAR);
    if (threadIdx.x == 0) {
        mbinit(mb0); mbinit(mb0 + 8);
        asm volatile("fence.proxy.async.shared::cta;" ::: "memory");
    }
    __syncthreads();
    unsigned pc[2] = {0, 0};
    int nt = blockIdx.x, tz = blockIdx.y;
    gemm_bulk(dsm,
              g_xthi + (size_t)tz * 8 * 4096, g_xtlo + (size_t)tz * 8 * 4096,
              g_WLhi[0] + (size_t)nt * 32 * 4096, g_WLlo[0] + (size_t)nt * 32 * 4096,
              8, g_xp + (size_t)tz * BB * 4096, 4096, nt * 64, pc);
}

// ---- weight prep: W [N][Kw] fp32 -> swizzled tile strips [ntile][nkTot][4096] hi/lo ----
__global__ void tsplitW(const float* __restrict__ W, bf16* __restrict__ dhi,
                        bf16* __restrict__ dlo, int Kw, int nkTot, int kcBase)
{
    int kc = blockIdx.x, nt = blockIdx.y;
    const float* Wb = W + (size_t)nt * 64 * Kw + kc * 64;
    size_t base = ((size_t)nt * nkTot + kcBase + kc) * 4096;
    for (int i = threadIdx.x; i < 4096; i += 256) {
        int c = i >> 6, r = i & 63;
        float v = Wb[(size_t)c * Kw + r];
        bf16 hi, lo;
        splitbf(v, &hi, &lo);
        size_t o = base + SW(r, c);
        dhi[o] = hi; dlo[o] = lo;
    }
}

// ---- embed all timesteps into tiles ----
__global__ void embed_k(const int* __restrict__ tgt, const float* __restrict__ emb)
{
    int idx = blockIdx.x * blockDim.x + threadIdx.x;
    if (idx >= TT * BB * EE) return;
    int e = idx & 511, tb = idx >> 9;
    int b = tb & 63, t = tb >> 6;
    int tok = tgt[t * BB + b];
    float v = emb[(size_t)tok * EE + e];
    size_t o = ((size_t)t * 8 + (e >> 6)) * 4096 + SW(b, e & 63);
    bf16 hi, lo;
    splitbf(v, &hi, &lo);
    g_xthi[o] = hi; g_xtlo[o] = lo;
}

// ---- init state ----
__global__ void init_k(const float* __restrict__ out0, const float* __restrict__ hinit)
{
    int idx = blockIdx.x * blockDim.x + threadIdx.x;
    if (idx >= BB * HH) return;
    int b = idx >> 10, j = idx & 1023;
    g_c[idx] = 0.f; g_c[BB * HH + idx] = 0.f;
    awr(g_a1hi, g_a1lo, 16, b, j, hinit[(size_t)BB * HH + idx]);  // h1 init
    awr(g_a0hi, g_a0lo, 8, b, j, hinit[idx]);                     // h0 init
    if (j < 512)
        awr(g_a0hi, g_a0lo, 0, b, j, out0[(size_t)b * EE + j]);   // input feed init
}

extern "C" void kernel_launch(void* const* d_in, const int* in_sizes, int n_in,
                              void* d_out, int out_size)
{
    const int*   tgt   = (const int*)d_in[0];
    const float* enc   = (const float*)d_in[1];
    const float* emb   = (const float*)d_in[2];
    const float* out0  = (const float*)d_in[3];
    const float* hinit = (const float*)d_in[4];
    const float* Wih   = (const float*)d_in[5];
    const float* Whh   = (const float*)d_in[6];
    const float* bih   = (const float*)d_in[7];
    const float* bhh   = (const float*)d_in[8];
    const float* W1    = (const float*)d_in[9];
    const float* b1    = (const float*)d_in[10];
    const float* W2    = (const float*)d_in[11];
    const float* b2    = (const float*)d_in[12];
    float* out = (float*)d_out;

    static int attr_done = 0;
    cudaFuncSetAttribute(mega, cudaFuncAttributeMaxDynamicSharedMemorySize, SM_TOTAL);
    cudaFuncSetAttribute(gemm_pre, cudaFuncAttributeMaxDynamicSharedMemorySize, SM_PRE_TOTAL);
    (void)attr_done;

    bf16 *W0hi, *W0lo, *W1hi, *W1lo;
    void* barp;
    cudaGetSymbolAddress((void**)&W0hi, g_WLhi);
    cudaGetSymbolAddress((void**)&W0lo, g_WLlo);
    W1hi = W0hi + (size_t)64 * 32 * 4096;
    W1lo = W0lo + (size_t)64 * 32 * 4096;
    bf16 *Wqh, *Wql, *W2h, *W2l;
    cudaGetSymbolAddress((void**)&Wqh, g_Wqhi);
    cudaGetSymbolAddress((void**)&Wql, g_Wqlo);
    cudaGetSymbolAddress((void**)&W2h, g_W2hi);
    cudaGetSymbolAddress((void**)&W2l, g_W2lo);
    cudaGetSymbolAddress(&barp, g_bar);

    // weight strips: LSTM layer l: Wih -> chunks 0..15, Whh -> chunks 16..31
    tsplitW<<<dim3(16, 64), 256>>>(Wih,                           W0hi, W0lo, 1024, 32, 0);
    tsplitW<<<dim3(16, 64), 256>>>(Whh,                           W0hi, W0lo, 1024, 32, 16);
    tsplitW<<<dim3(16, 64), 256>>>(Wih + (size_t)4096 * 1024,     W1hi, W1lo, 1024, 32, 0);
    tsplitW<<<dim3(16, 64), 256>>>(Whh + (size_t)4096 * 1024,     W1hi, W1lo, 1024, 32, 16);
    tsplitW<<<dim3(16, 16), 256>>>(W1, Wqh, Wql, 1024, 16, 0);
    tsplitW<<<dim3(32, 8),  256>>>(W2, W2h, W2l, 2048, 32, 0);
    embed_k<<<(TT * BB * EE + 255) / 256, 256>>>(tgt, emb);
    init_k<<<(BB * HH + 255) / 256, 256>>>(out0, hinit);
    gemm_pre<<<dim3(64, 64), 256, SM_PRE_TOTAL>>>();

    cudaMemsetAsync(barp, 0, sizeof(unsigned));
    mega<<<NBLK, 256, SM_TOTAL>>>(enc, bih, bhh, b1, b2, out);
}